// round 3
// baseline (speedup 1.0000x reference)
#include <cuda_runtime.h>
#include <cuda_bf16.h>

// Problem constants from the reference (MAP = H = W = 64).
#define HH 64
#define WW 64
#define HWSZ 4096
#define MAPC 64

// Fused kernel: one block per GT.
// Phase 1: all threads scan preds, block-argmin on packed key (dist2<<10 | j).
//          Integer squared distance preserves jnp's sqrt-float argmin ordering
//          (sqrt monotone; float32 sqrt of distinct ints <= 7938 never collides),
//          and the packed j reproduces first-index tie-breaking.
// Phase 2: thread-per-channel gather: 3x3 max + zero-padded bilinear sample.
__global__ void __launch_bounds__(512, 2)
rp_kernel(const float* __restrict__ params,
          const float* __restrict__ offsets,
          const int*   __restrict__ vgt_bid,
          const int*   __restrict__ vgt_cen,
          const int*   __restrict__ pred_bid,
          const int*   __restrict__ pred_cyx,
          float* __restrict__ out,
          int n_gt, int n_pred, int C)
{
    const int gt  = blockIdx.x;
    const int tid = threadIdx.x;

    __shared__ unsigned s_warpmin[16];
    __shared__ int   s_b, s_cy, s_cx;
    __shared__ float s_y, s_x;

    const int gb = vgt_bid[gt];
    const int gy = vgt_cen[2 * gt];
    const int gx = vgt_cen[2 * gt + 1];

    // ---- Phase 1: matching ----
    unsigned best = 0xFFFFFFFFu;
    for (int j = tid; j < n_pred; j += blockDim.x) {
        int dy = pred_cyx[2 * j]     - gy;
        int dx = pred_cyx[2 * j + 1] - gx;
        // mismatched batch -> huge-but-finite dist so all-mismatch still yields
        // smallest j (matches jnp.argmin over all-inf returning 0).
        unsigned d2 = (pred_bid[j] == gb) ? (unsigned)(dy * dy + dx * dx)
                                          : 0x00040000u;
        unsigned key = (d2 << 10) | (unsigned)j;   // d2 < 2^18, j < 1024
        best = min(best, key);
    }
    best = __reduce_min_sync(0xFFFFFFFFu, best);
    if ((tid & 31) == 0) s_warpmin[tid >> 5] = best;
    __syncthreads();
    if (tid == 0) {
        unsigned m = s_warpmin[0];
        int nw = (blockDim.x + 31) >> 5;
        for (int w = 1; w < nw; w++) m = min(m, s_warpmin[w]);
        int j  = (int)(m & 1023u);
        int py = min(max(pred_cyx[2 * j],     0), MAPC - 1);
        int px = min(max(pred_cyx[2 * j + 1], 0), MAPC - 1);
        int flat = py * MAPC + px;
        s_b  = gb;
        s_cy = py;
        s_cx = px;
        s_y = (float)py + offsets[((size_t)gb * 2 + 0) * HWSZ + flat];
        s_x = (float)px + offsets[((size_t)gb * 2 + 1) * HWSZ + flat];
        // centers_pred = (flat % MAP, flat // MAP), appended after the (n_gt, 2C) block
        out[(size_t)n_gt * 2 * C + 2 * gt]     = (float)(flat % MAPC);
        out[(size_t)n_gt * 2 * C + 2 * gt + 1] = (float)(flat / MAPC);
    }
    __syncthreads();

    // ---- Phase 2: per-channel gather ----
    const int   b  = s_b;
    const int   cy = s_cy;
    const int   cx = s_cx;
    const float y  = s_y;
    const float x  = s_x;

    const float y0f = floorf(y), x0f = floorf(x);
    const float wy1 = y - y0f,   wx1 = x - x0f;
    const float wy0 = 1.f - wy1, wx0 = 1.f - wx1;

    const int ry[3] = { max(cy - 1, 0), cy, min(cy + 1, HH - 1) };
    const int rx[3] = { max(cx - 1, 0), cx, min(cx + 1, WW - 1) };

    for (int c = tid; c < C; c += blockDim.x) {
        const float* bp = params + ((size_t)b * C + c) * HWSZ;

        // 3x3 clipped max (duplicates from clipping are harmless for max)
        float mx = -3.402823466e38f;
        #pragma unroll
        for (int iy = 0; iy < 3; iy++) {
            const float* rowp = bp + ry[iy] * WW;
            #pragma unroll
            for (int ix = 0; ix < 3; ix++)
                mx = fmaxf(mx, rowp[rx[ix]]);
        }

        // bilinear with zero-fill OOB corners (reference semantics)
        float v = 0.f;
        #pragma unroll
        for (int iy = 0; iy < 2; iy++) {
            float yy = y0f + (float)iy;
            float wy = iy ? wy1 : wy0;
            #pragma unroll
            for (int ix = 0; ix < 2; ix++) {
                float xx = x0f + (float)ix;
                float wx = ix ? wx1 : wx0;
                float cv = 0.f;
                if (yy >= 0.f && yy <= (float)(HH - 1) &&
                    xx >= 0.f && xx <= (float)(WW - 1)) {
                    int yi = (int)yy;   // yy in [0,63] here, truncation == floor
                    int xi = (int)xx;
                    cv = bp[yi * WW + xi];
                }
                v += wy * wx * cv;
            }
        }

        out[(size_t)gt * 2 * C + c]     = v;   // params_pred (bilinear)
        out[(size_t)gt * 2 * C + C + c] = mx;  // params_pred_max
    }
}

extern "C" void kernel_launch(void* const* d_in, const int* in_sizes, int n_in,
                              void* d_out, int out_size)
{
    const float* params   = (const float*)d_in[0];  // (B, C, 64, 64) f32
    const float* offsets  = (const float*)d_in[1];  // (B, 2, 64, 64) f32
    const int*   vgt_bid  = (const int*)d_in[2];    // (n_gt,)
    const int*   vgt_cen  = (const int*)d_in[3];    // (n_gt, 2)
    const int*   pred_bid = (const int*)d_in[4];    // (n_pred,)
    const int*   pred_cyx = (const int*)d_in[5];    // (n_pred, 2)
    float* out = (float*)d_out;

    const int n_gt   = in_sizes[2];
    const int n_pred = in_sizes[4];
    const int B      = in_sizes[1] / (2 * HWSZ);
    const int C      = in_sizes[0] / (B * HWSZ);

    rp_kernel<<<n_gt, 512>>>(params, offsets, vgt_bid, vgt_cen,
                             pred_bid, pred_cyx, out, n_gt, n_pred, C);
}

// round 5
// speedup vs baseline: 1.0478x; 1.0478x over previous
#include <cuda_runtime.h>
#include <cuda_bf16.h>

// Problem constants from the reference (MAP = H = W = 64).
#define HH 64
#define WW 64
#define HWSZ 4096
#define MAPC 64
#define NSPLIT 4

// Extract component i (0..3) of a float4 via predicated selects (i is
// block-uniform -> no divergence, just SELs).
__device__ __forceinline__ float comp4(float4 v, int i) {
    float ab = (i & 1) ? v.y : v.x;
    float cd = (i & 1) ? v.w : v.z;
    return (i & 2) ? cd : ab;
}
__device__ __forceinline__ float comp8(float4 a, float4 b, int i) {
    return (i & 4) ? comp4(b, i) : comp4(a, i);
}

// One block per (gt, channel-chunk). 128 threads.
// Phase 1 (all threads): block-argmin matching on packed key (dist2<<10 | j).
// Phase 2 (one channel per thread): 3x3 max + zero-padded bilinear, using
// block-uniform aligned float4 window loads (1-2 per row instead of 2-3
// scalar LDGs) — every load here is fully divergent across the warp
// (16KB channel stride), so wavefront cost scales with LDG *instruction*
// count, which this layout minimizes.
__global__ void __launch_bounds__(128, 8)
rp_kernel(const float* __restrict__ params,
          const float* __restrict__ offsets,
          const int*   __restrict__ vgt_bid,
          const int*   __restrict__ vgt_cen,
          const int*   __restrict__ pred_bid,
          const int*   __restrict__ pred_cyx,
          float* __restrict__ out,
          int n_gt, int n_pred, int C)
{
    const int gt    = blockIdx.x;
    const int chunk = blockIdx.y;
    const int tid   = threadIdx.x;

    __shared__ unsigned s_warpmin[4];
    __shared__ int   s_b, s_cy, s_cx;
    __shared__ float s_y, s_x;

    const int gb = vgt_bid[gt];
    const int gy = vgt_cen[2 * gt];
    const int gx = vgt_cen[2 * gt + 1];

    // ---- Phase 1: matching (cheap, recomputed per chunk) ----
    unsigned best = 0xFFFFFFFFu;
    for (int j = tid; j < n_pred; j += blockDim.x) {
        int dy = pred_cyx[2 * j]     - gy;
        int dx = pred_cyx[2 * j + 1] - gx;
        // mismatched batch -> huge-but-finite dist; all-mismatch then yields
        // smallest j (matches jnp.argmin over all-inf returning 0).
        unsigned d2 = (pred_bid[j] == gb) ? (unsigned)(dy * dy + dx * dx)
                                          : 0x00040000u;
        best = min(best, (d2 << 10) | (unsigned)j);   // d2 < 2^18, j < 1024
    }
    best = __reduce_min_sync(0xFFFFFFFFu, best);
    if ((tid & 31) == 0) s_warpmin[tid >> 5] = best;
    __syncthreads();
    if (tid == 0) {
        unsigned m = min(min(s_warpmin[0], s_warpmin[1]),
                         min(s_warpmin[2], s_warpmin[3]));
        int j  = (int)(m & 1023u);
        int py = min(max(pred_cyx[2 * j],     0), MAPC - 1);
        int px = min(max(pred_cyx[2 * j + 1], 0), MAPC - 1);
        int flat = py * MAPC + px;
        s_b  = gb;
        s_cy = py;
        s_cx = px;
        s_y = (float)py + offsets[((size_t)gb * 2 + 0) * HWSZ + flat];
        s_x = (float)px + offsets[((size_t)gb * 2 + 1) * HWSZ + flat];
        if (chunk == 0) {
            // centers_pred appended after the (n_gt, 2C) block
            out[(size_t)n_gt * 2 * C + 2 * gt]     = (float)(flat % MAPC);
            out[(size_t)n_gt * 2 * C + 2 * gt + 1] = (float)(flat / MAPC);
        }
    }
    __syncthreads();

    // ---- Phase 2: per-channel gather (all geometry block-uniform) ----
    const int   b  = s_b;
    const int   cy = s_cy;
    const int   cx = s_cx;
    const float y  = s_y;
    const float x  = s_x;

    // 3x3 max region: contiguous cols [xlo..xhi], rows [ylo..yhi]
    const int xlo = max(cx - 1, 0), xhi = min(cx + 1, WW - 1);
    const int ylo = max(cy - 1, 0), yhi = min(cy + 1, HH - 1);
    const int a0   = xlo & ~3;                 // 16B-aligned window start
    const bool nB  = (xhi - a0) > 3;           // need 2nd float4 (uniform)
    const int i0   = xlo - a0;
    const int nCol = xhi - xlo;                // 0..2 extra cols

    // bilinear geometry
    const float y0f = floorf(y), x0f = floorf(x);
    const float wy1 = y - y0f,   wx1 = x - x0f;
    const float wy0 = 1.f - wy1, wx0 = 1.f - wx1;
    const int yi0 = (int)y0f, xi0 = (int)x0f;
    const bool vx0 = (xi0     >= 0) && (xi0     <= WW - 1);
    const bool vx1 = (xi0 + 1 >= 0) && (xi0 + 1 <= WW - 1);
    const bool vy0 = (yi0     >= 0) && (yi0     <= HH - 1);
    const bool vy1 = (yi0 + 1 >= 0) && (yi0 + 1 <= HH - 1);
    const bool anyx = vx0 || vx1;
    const int  bxlo = vx0 ? xi0 : (vx1 ? xi0 + 1 : 0);
    const int  bxhi = vx1 ? xi0 + 1 : (vx0 ? xi0 : 0);
    const int  b0   = bxlo & ~3;
    const bool nB2  = (bxhi - b0) > 3;
    const int  j0   = xi0 - b0;                // left-corner window index

    const int CH = (C + NSPLIT - 1) / NSPLIT;  // channels per chunk
    const int c  = chunk * CH + tid;

    if (tid < CH && c < C) {
        const float* bp = params + ((size_t)b * C + c) * HWSZ;

        // ---- 3x3 max via aligned float4 window loads ----
        float mx = -3.402823466e38f;
        #pragma unroll
        for (int rr = 0; rr < 3; rr++) {
            int r = ylo + rr;
            if (r > yhi) break;                 // uniform
            const float4* q = (const float4*)(bp + r * WW + a0);
            float4 A = q[0];
            float4 Bv = A;
            if (nB) Bv = q[1];                  // uniform predicated load
            mx = fmaxf(mx, comp8(A, Bv, i0));
            if (nCol > 0) mx = fmaxf(mx, comp8(A, Bv, i0 + 1));
            if (nCol > 1) mx = fmaxf(mx, comp8(A, Bv, i0 + 2));
        }

        // ---- bilinear with zero-fill OOB corners ----
        float c00 = 0.f, c01 = 0.f, c10 = 0.f, c11 = 0.f;
        if (anyx) {
            if (vy0) {
                const float4* q = (const float4*)(bp + yi0 * WW + b0);
                float4 A = q[0];
                float4 Bv = A;
                if (nB2) Bv = q[1];
                if (vx0) c00 = comp8(A, Bv, j0);
                if (vx1) c01 = comp8(A, Bv, j0 + 1);
            }
            if (vy1) {
                const float4* q = (const float4*)(bp + (yi0 + 1) * WW + b0);
                float4 A = q[0];
                float4 Bv = A;
                if (nB2) Bv = q[1];
                if (vx0) c10 = comp8(A, Bv, j0);
                if (vx1) c11 = comp8(A, Bv, j0 + 1);
            }
        }
        // exact reference accumulation order
        float v = wy0 * wx0 * c00 + wy0 * wx1 * c01
                + wy1 * wx0 * c10 + wy1 * wx1 * c11;

        out[(size_t)gt * 2 * C + c]     = v;   // params_pred (bilinear)
        out[(size_t)gt * 2 * C + C + c] = mx;  // params_pred_max
    }
}

extern "C" void kernel_launch(void* const* d_in, const int* in_sizes, int n_in,
                              void* d_out, int out_size)
{
    const float* params   = (const float*)d_in[0];  // (B, C, 64, 64) f32
    const float* offsets  = (const float*)d_in[1];  // (B, 2, 64, 64) f32
    const int*   vgt_bid  = (const int*)d_in[2];    // (n_gt,)
    const int*   vgt_cen  = (const int*)d_in[3];    // (n_gt, 2)
    const int*   pred_bid = (const int*)d_in[4];    // (n_pred,)
    const int*   pred_cyx = (const int*)d_in[5];    // (n_pred, 2)
    float* out = (float*)d_out;

    const int n_gt   = in_sizes[2];
    const int n_pred = in_sizes[4];
    const int B      = in_sizes[1] / (2 * HWSZ);
    const int C      = in_sizes[0] / (B * HWSZ);

    dim3 grid(n_gt, NSPLIT);
    rp_kernel<<<grid, 128>>>(params, offsets, vgt_bid, vgt_cen,
                             pred_bid, pred_cyx, out, n_gt, n_pred, C);
}